// round 8
// baseline (speedup 1.0000x reference)
#include <cuda_runtime.h>
#include <cuda_fp16.h>

// ---------------------------------------------------------------------------
// DummyGAT: h = x@W; GAT edge softmax + aggregation; out = mean(relu(agg)@W_lin + b_lin)
// N = 100000 nodes, E = 1.6M edges, IN=128, HID=64, OUT=64
// 4 launches: [gemm+hist] -> [lookback scan] -> [scatter] -> [agg+final]
// ---------------------------------------------------------------------------

#define N_MAX 100000
#define E_MAX 1600000
#define SCAN_BLOCKS 391   // ceil(100000/256)

__device__ __align__(256) __half g_h2[N_MAX * 64];    // h in fp16 (gather operand)
__device__ __align__(256) float  g_asrc[N_MAX];
__device__ __align__(256) float  g_adst[N_MAX];
__device__ __align__(256) int    g_deg[N_MAX];        // in-degree   (zeroed by agg at end)
__device__ __align__(256) int    g_cursor[N_MAX];     // scan: start; after scatter: end
__device__ __align__(256) int    g_csrc[E_MAX];       // CSR: src per (dst-sorted) edge
__device__ __align__(256) unsigned long long g_pkt[SCAN_BLOCKS]; // lookback (flag<<32|val), zeroed by scatter
__device__ __align__(256) float  g_s[64];             // node-sum accumulator (zeroed by agg)
__device__ int g_done;                                // zeroed by agg

__device__ __forceinline__ float lrelu(float x) { return x > 0.f ? x : 0.2f * x; }

// ---------------------------------------------------------------------------
// Kernel 1: blocks [0,GB): h = x@W fused with attention scores (k-major x tile,
// so the inner loop is 2x LDS.128 per k — FFMA-bound). blocks [GB,..): in-degree
// histogram (independent of gemm; overlaps under the FFMA-bound gemm blocks).
// ---------------------------------------------------------------------------
__global__ void gemm_hist_kernel(const float* __restrict__ x, const float* __restrict__ W,
                                 const float* __restrict__ att_src, const float* __restrict__ att_dst,
                                 const int* __restrict__ ei, int N, int E, int GB) {
    if (blockIdx.x >= GB) {               // ---- histogram part ----
        int i = (blockIdx.x - GB) * 256 + threadIdx.x;
        if (i < E) atomicAdd(&g_deg[ei[E + i]], 1);
        return;
    }
    // ---- gemm part ----
    int row0 = blockIdx.x * 64;
    if (blockIdx.x == 0 && threadIdx.x < 64) g_s[threadIdx.x] = 0.f;   // (idempotent w/ agg cleanup)

    __shared__ float xs[64 * 68];    // k-major: xs[k*68 + r]
    __shared__ float ws[64 * 64];    // [k][c]
    int tx = threadIdx.x & 15;       // col group (4 cols)
    int ty = threadIdx.x >> 4;       // row group (4 rows)
    float acc[4][4] = {};

    for (int k0 = 0; k0 < 128; k0 += 64) {
        #pragma unroll
        for (int i = 0; i < 4; i++) {
            int idx = threadIdx.x + i * 256;
            int r = idx >> 4, c4 = idx & 15;
            int grow = row0 + r;
            float4 v = make_float4(0.f, 0.f, 0.f, 0.f);
            if (grow < N) v = ((const float4*)x)[grow * 32 + (k0 >> 2) + c4];
            int kk = c4 * 4;
            xs[(kk + 0) * 68 + r] = v.x;
            xs[(kk + 1) * 68 + r] = v.y;
            xs[(kk + 2) * 68 + r] = v.z;
            xs[(kk + 3) * 68 + r] = v.w;
        }
        #pragma unroll
        for (int i = 0; i < 4; i++) {
            int idx = threadIdx.x + i * 256;
            ((float4*)ws)[idx] = ((const float4*)(W + k0 * 64))[idx];
        }
        __syncthreads();

        #pragma unroll 16
        for (int k = 0; k < 64; k++) {
            float4 xv = *(float4*)&xs[k * 68 + ty * 4];   // broadcast: 2 addrs/warp
            float4 wv = *(float4*)&ws[k * 64 + tx * 4];
            acc[0][0] += xv.x * wv.x; acc[0][1] += xv.x * wv.y; acc[0][2] += xv.x * wv.z; acc[0][3] += xv.x * wv.w;
            acc[1][0] += xv.y * wv.x; acc[1][1] += xv.y * wv.y; acc[1][2] += xv.y * wv.z; acc[1][3] += xv.y * wv.w;
            acc[2][0] += xv.z * wv.x; acc[2][1] += xv.z * wv.y; acc[2][2] += xv.z * wv.z; acc[2][3] += xv.z * wv.w;
            acc[3][0] += xv.w * wv.x; acc[3][1] += xv.w * wv.y; acc[3][2] += xv.w * wv.z; acc[3][3] += xv.w * wv.w;
        }
        __syncthreads();
    }

    // attention scores via width-16 shuffle reduce
    float4 as4 = ((const float4*)att_src)[tx];
    float4 ad4 = ((const float4*)att_dst)[tx];
    #pragma unroll
    for (int i = 0; i < 4; i++) {
        float pa = acc[i][0] * as4.x + acc[i][1] * as4.y + acc[i][2] * as4.z + acc[i][3] * as4.w;
        float pd = acc[i][0] * ad4.x + acc[i][1] * ad4.y + acc[i][2] * ad4.z + acc[i][3] * ad4.w;
        #pragma unroll
        for (int off = 8; off; off >>= 1) {
            pa += __shfl_down_sync(0xffffffffu, pa, off, 16);
            pd += __shfl_down_sync(0xffffffffu, pd, off, 16);
        }
        if (tx == 0) {
            int r = row0 + ty * 4 + i;
            if (r < N) { g_asrc[r] = pa; g_adst[r] = pd; }
        }
    }

    #pragma unroll
    for (int i = 0; i < 4; i++) {
        int r = row0 + ty * 4 + i;
        if (r >= N) continue;
        union { __half2 h[2]; float2 f; } u;
        u.h[0] = __floats2half2_rn(acc[i][0], acc[i][1]);
        u.h[1] = __floats2half2_rn(acc[i][2], acc[i][3]);
        ((float2*)g_h2)[r * 16 + tx] = u.f;
    }
}

// ---------------------------------------------------------------------------
// Kernel 2: single-pass exclusive scan of g_deg -> g_cursor (decoupled lookback).
// All 391 blocks fit in one wave (no forward-progress hazard).
// ---------------------------------------------------------------------------
#define FLAG_AGG  (1ull << 32)
#define FLAG_INCL (2ull << 32)

__global__ void scan_kernel(int N) {
    int t = threadIdx.x;
    int bid = blockIdx.x;
    int g = bid * 256 + t;
    int lane = t & 31, w = t >> 5;
    int v = (g < N) ? g_deg[g] : 0;
    int incl = v;
    #pragma unroll
    for (int off = 1; off < 32; off <<= 1) {
        int nv = __shfl_up_sync(0xffffffffu, incl, off);
        if (lane >= off) incl += nv;
    }
    __shared__ int wsum[8];
    if (lane == 31) wsum[w] = incl;
    __syncthreads();
    if (t < 8) {
        int xw = wsum[t];
        int in2 = xw;
        #pragma unroll
        for (int off = 1; off < 8; off <<= 1) {
            int nv = __shfl_up_sync(0xffu, in2, off);
            if (t >= off) in2 += nv;
        }
        wsum[t] = in2 - xw;   // exclusive warp offsets
    }
    __syncthreads();
    int excl = incl - v + wsum[w];

    __shared__ int sPrefix;
    __shared__ int sTotal;
    if (t == 255) sTotal = excl + v;
    __syncthreads();
    if (t == 0) {
        unsigned long long total = (unsigned long long)(unsigned)sTotal;
        if (bid == 0) {
            atomicExch(&g_pkt[0], total | FLAG_INCL);
            sPrefix = 0;
        } else {
            atomicExch(&g_pkt[bid], total | FLAG_AGG);
            long long run = 0;
            int j = bid - 1;
            while (true) {
                unsigned long long p;
                do { p = atomicAdd(&g_pkt[j], 0ull); } while ((p >> 32) == 0);
                run += (unsigned)(p & 0xffffffffu);
                if (p & FLAG_INCL) break;
                j--;
            }
            atomicExch(&g_pkt[bid], (total + (unsigned long long)(unsigned)run) | FLAG_INCL);
            sPrefix = (int)run;
        }
    }
    __syncthreads();
    if (g < N) g_cursor[g] = excl + sPrefix;
}

// ---------------------------------------------------------------------------
// Kernel 3: scatter edges into CSR (dst-sorted src list); also re-zeroes g_pkt
// for the next launch. After this kernel g_cursor[d] == row end.
// ---------------------------------------------------------------------------
__global__ void scatter_kernel(const int* __restrict__ ei, int E) {
    int i = blockIdx.x * blockDim.x + threadIdx.x;
    if (i < SCAN_BLOCKS) g_pkt[i] = 0ull;
    if (i >= E) return;
    int s = ei[i];
    int d = ei[E + i];
    int pos = atomicAdd(&g_cursor[d], 1);
    g_csrc[pos] = s;
}

// ---------------------------------------------------------------------------
// Kernel 4: warp-per-node gather aggregation (no global feature atomics).
// start = g_cursor[node] - deg. Fused: denom, normalize, bias, relu, node-sum,
// and final 64x64 matvec in the last-done block. Cleans g_deg/g_s/g_done.
// ---------------------------------------------------------------------------
__global__ void agg_kernel(const float* __restrict__ bias,
                           const float* __restrict__ W_lin, const float* __restrict__ b_lin,
                           float* __restrict__ out, float invN, int N) {
    __shared__ float sm[64];
    __shared__ float sf[64];
    __shared__ int lastFlag;
    int t = threadIdx.x;
    if (t < 64) sm[t] = 0.f;
    __syncthreads();

    int wid = t >> 5, lane = t & 31;
    int half = lane >> 4, l16 = lane & 15;
    int node = blockIdx.x * 8 + wid;

    if (node < N) {
        int deg = g_deg[node];
        int start = g_cursor[node] - deg;
        if (lane == 0) g_deg[node] = 0;        // cleanup for next launch's histogram
        float adst_n = g_adst[node];
        float asrc_n = g_asrc[node];
        float4 acc = make_float4(0.f, 0.f, 0.f, 0.f);
        float dsum = 0.f;

        // self loop (half A accumulates the feature part)
        float e_self = __expf(lrelu(asrc_n + adst_n));
        if (half == 0) {
            float2 p = ((const float2*)g_h2)[node * 16 + l16];
            float2 lo = __half22float2(((const __half2*)&p)[0]);
            float2 hi = __half22float2(((const __half2*)&p)[1]);
            acc.x += lo.x * e_self; acc.y += lo.y * e_self;
            acc.z += hi.x * e_self; acc.w += hi.y * e_self;
        }

        for (int c0 = 0; c0 < deg; c0 += 32) {
            int k = c0 + lane;
            int s = 0; float e = 0.f;
            if (k < deg) {
                s = g_csrc[start + k];
                e = __expf(lrelu(g_asrc[s] + adst_n));
                dsum += e;
            }
            int m = min(32, deg - c0);
            int steps = (m + 1) >> 1;
            for (int st2 = 0; st2 < steps; st2++) {
                int j = st2 * 2 + half;
                int jj = j < m ? j : 0;
                int ss = __shfl_sync(0xffffffffu, s, jj);
                float ee = __shfl_sync(0xffffffffu, e, jj);
                if (j < m) {
                    float2 p = ((const float2*)g_h2)[ss * 16 + l16];
                    float2 lo = __half22float2(((const __half2*)&p)[0]);
                    float2 hi = __half22float2(((const __half2*)&p)[1]);
                    acc.x += lo.x * ee; acc.y += lo.y * ee;
                    acc.z += hi.x * ee; acc.w += hi.y * ee;
                }
            }
        }

        // denom: full-warp reduce + self term
        #pragma unroll
        for (int off = 16; off; off >>= 1)
            dsum += __shfl_xor_sync(0xffffffffu, dsum, off);
        float denom = dsum + e_self;

        // combine the two halves' feature accumulators (same cols)
        acc.x += __shfl_down_sync(0xffffffffu, acc.x, 16);
        acc.y += __shfl_down_sync(0xffffffffu, acc.y, 16);
        acc.z += __shfl_down_sync(0xffffffffu, acc.z, 16);
        acc.w += __shfl_down_sync(0xffffffffu, acc.w, 16);

        if (half == 0) {
            float inv = 1.f / denom;
            float4 bv = ((const float4*)bias)[l16];
            atomicAdd(&sm[l16 * 4 + 0], fmaxf(acc.x * inv + bv.x, 0.f));
            atomicAdd(&sm[l16 * 4 + 1], fmaxf(acc.y * inv + bv.y, 0.f));
            atomicAdd(&sm[l16 * 4 + 2], fmaxf(acc.z * inv + bv.z, 0.f));
            atomicAdd(&sm[l16 * 4 + 3], fmaxf(acc.w * inv + bv.w, 0.f));
        }
    }
    __syncthreads();
    if (t < 16) {
        float4 v = *(float4*)&sm[t * 4];
        float* dst = g_s + t * 4;
        asm volatile("red.global.add.v4.f32 [%0], {%1,%2,%3,%4};"
                     :: "l"(dst), "f"(v.x), "f"(v.y), "f"(v.z), "f"(v.w)
                     : "memory");
        __threadfence();
    }
    __syncthreads();
    if (t == 0) {
        int old = atomicAdd(&g_done, 1);
        lastFlag = (old == (int)gridDim.x - 1);
    }
    __syncthreads();

    if (lastFlag) {
        __threadfence();   // acquire: make all blocks' g_s reds visible
        if (t < 64) {
            float v;
            asm volatile("ld.global.cg.f32 %0, [%1];" : "=f"(v) : "l"(g_s + t));
            sf[t] = v;
        }
        __syncthreads();
        if (t < 64) {
            g_s[t] = 0.f;                       // cleanup for next launch
            float acc2 = b_lin[t];
            #pragma unroll 8
            for (int c = 0; c < 64; c++)
                acc2 += (sf[c] * invN) * W_lin[c * 64 + t];
            out[t] = acc2;
        }
        if (t == 0) g_done = 0;                 // cleanup for next launch
    }
}

// ---------------------------------------------------------------------------
extern "C" void kernel_launch(void* const* d_in, const int* in_sizes, int n_in,
                              void* d_out, int out_size) {
    const float* x       = (const float*)d_in[0];
    const int*   ei      = (const int*)d_in[1];
    const float* W       = (const float*)d_in[2];
    const float* att_src = (const float*)d_in[3];
    const float* att_dst = (const float*)d_in[4];
    const float* bias    = (const float*)d_in[5];
    const float* W_lin   = (const float*)d_in[6];
    const float* b_lin   = (const float*)d_in[7];

    int N = in_sizes[0] / 128;   // 100000
    int E = in_sizes[1] / 2;     // 1600000
    int GB = (N + 63) / 64;      // gemm blocks
    int HB = (E + 255) / 256;    // hist blocks

    gemm_hist_kernel<<<GB + HB, 256>>>(x, W, att_src, att_dst, ei, N, E, GB);
    scan_kernel<<<(N + 255) / 256, 256>>>(N);
    scatter_kernel<<<(E + 255) / 256, 256>>>(ei, E);
    agg_kernel<<<(N + 7) / 8, 256>>>(bias, W_lin, b_lin, (float*)d_out, 1.0f / (float)N, N);
}

// round 9
// speedup vs baseline: 1.7872x; 1.7872x over previous
#include <cuda_runtime.h>
#include <cuda_fp16.h>

// ---------------------------------------------------------------------------
// DummyGAT: h = x@W; GAT edge softmax + aggregation; out = mean(relu(agg)@W_lin + b_lin)
// N = 100000 nodes, E = 1.6M edges, IN=128, HID=64, OUT=64
// 4 launches: [gemm+hist] -> [lookback scan] -> [scatter] -> [agg+final]
// agg: shuffle-free prefetched gather, 64-way-spread block reduction.
// ---------------------------------------------------------------------------

#define N_MAX 100000
#define E_MAX 1600000
#define SCAN_BLOCKS 391   // ceil(100000/256)

__device__ __align__(256) __half g_h2[N_MAX * 64];    // h in fp16 (gather operand)
__device__ __align__(256) float  g_asrc[N_MAX];
__device__ __align__(256) float  g_adst[N_MAX];
__device__ __align__(256) int    g_deg[N_MAX];        // in-degree (zeroed by agg)
__device__ __align__(256) int    g_start[N_MAX];      // CSR row start (from scan)
__device__ __align__(256) int    g_cursor[N_MAX];     // scatter cursor
__device__ __align__(256) int    g_csrc[E_MAX];       // CSR: src per (dst-sorted) edge
__device__ __align__(256) unsigned long long g_pkt[SCAN_BLOCKS]; // lookback, zeroed by scatter
__device__ __align__(256) float  g_smulti[64 * 64];   // 64-way-spread node-sum slots (zeroed by agg)
__device__ int g_done;                                // zeroed by agg

__device__ __forceinline__ float lrelu(float x) { return x > 0.f ? x : 0.2f * x; }

// ---------------------------------------------------------------------------
// Kernel 1: blocks [0,GB): h = x@W + attention scores (k-major x tile -> FFMA-bound).
// blocks [GB,..): in-degree histogram (overlaps under the gemm blocks).
// ---------------------------------------------------------------------------
__global__ void gemm_hist_kernel(const float* __restrict__ x, const float* __restrict__ W,
                                 const float* __restrict__ att_src, const float* __restrict__ att_dst,
                                 const int* __restrict__ ei, int N, int E, int GB) {
    if (blockIdx.x >= GB) {               // ---- histogram part ----
        int i = (blockIdx.x - GB) * 256 + threadIdx.x;
        if (i < E) atomicAdd(&g_deg[ei[E + i]], 1);
        return;
    }
    // ---- gemm part ----
    int row0 = blockIdx.x * 64;

    __shared__ float xs[64 * 68];    // k-major: xs[k*68 + r]
    __shared__ float ws[64 * 64];    // [k][c]
    int tx = threadIdx.x & 15;       // col group (4 cols)
    int ty = threadIdx.x >> 4;       // row group (4 rows)
    float acc[4][4] = {};

    for (int k0 = 0; k0 < 128; k0 += 64) {
        #pragma unroll
        for (int i = 0; i < 4; i++) {
            int idx = threadIdx.x + i * 256;
            int r = idx >> 4, c4 = idx & 15;
            int grow = row0 + r;
            float4 v = make_float4(0.f, 0.f, 0.f, 0.f);
            if (grow < N) v = ((const float4*)x)[grow * 32 + (k0 >> 2) + c4];
            int kk = c4 * 4;
            xs[(kk + 0) * 68 + r] = v.x;
            xs[(kk + 1) * 68 + r] = v.y;
            xs[(kk + 2) * 68 + r] = v.z;
            xs[(kk + 3) * 68 + r] = v.w;
        }
        #pragma unroll
        for (int i = 0; i < 4; i++) {
            int idx = threadIdx.x + i * 256;
            ((float4*)ws)[idx] = ((const float4*)(W + k0 * 64))[idx];
        }
        __syncthreads();

        #pragma unroll 16
        for (int k = 0; k < 64; k++) {
            float4 xv = *(float4*)&xs[k * 68 + ty * 4];   // broadcast: 2 addrs/warp
            float4 wv = *(float4*)&ws[k * 64 + tx * 4];
            acc[0][0] += xv.x * wv.x; acc[0][1] += xv.x * wv.y; acc[0][2] += xv.x * wv.z; acc[0][3] += xv.x * wv.w;
            acc[1][0] += xv.y * wv.x; acc[1][1] += xv.y * wv.y; acc[1][2] += xv.y * wv.z; acc[1][3] += xv.y * wv.w;
            acc[2][0] += xv.z * wv.x; acc[2][1] += xv.z * wv.y; acc[2][2] += xv.z * wv.z; acc[2][3] += xv.z * wv.w;
            acc[3][0] += xv.w * wv.x; acc[3][1] += xv.w * wv.y; acc[3][2] += xv.w * wv.z; acc[3][3] += xv.w * wv.w;
        }
        __syncthreads();
    }

    // attention scores via width-16 shuffle reduce
    float4 as4 = ((const float4*)att_src)[tx];
    float4 ad4 = ((const float4*)att_dst)[tx];
    #pragma unroll
    for (int i = 0; i < 4; i++) {
        float pa = acc[i][0] * as4.x + acc[i][1] * as4.y + acc[i][2] * as4.z + acc[i][3] * as4.w;
        float pd = acc[i][0] * ad4.x + acc[i][1] * ad4.y + acc[i][2] * ad4.z + acc[i][3] * ad4.w;
        #pragma unroll
        for (int off = 8; off; off >>= 1) {
            pa += __shfl_down_sync(0xffffffffu, pa, off, 16);
            pd += __shfl_down_sync(0xffffffffu, pd, off, 16);
        }
        if (tx == 0) {
            int r = row0 + ty * 4 + i;
            if (r < N) { g_asrc[r] = pa; g_adst[r] = pd; }
        }
    }

    #pragma unroll
    for (int i = 0; i < 4; i++) {
        int r = row0 + ty * 4 + i;
        if (r >= N) continue;
        union { __half2 h[2]; float2 f; } u;
        u.h[0] = __floats2half2_rn(acc[i][0], acc[i][1]);
        u.h[1] = __floats2half2_rn(acc[i][2], acc[i][3]);
        ((float2*)g_h2)[r * 16 + tx] = u.f;
    }
}

// ---------------------------------------------------------------------------
// Kernel 2: single-pass exclusive scan of g_deg -> g_start & g_cursor
// (decoupled lookback; all 391 blocks co-resident in one wave).
// ---------------------------------------------------------------------------
#define FLAG_AGG  (1ull << 32)
#define FLAG_INCL (2ull << 32)

__global__ void scan_kernel(int N) {
    int t = threadIdx.x;
    int bid = blockIdx.x;
    int g = bid * 256 + t;
    int lane = t & 31, w = t >> 5;
    int v = (g < N) ? g_deg[g] : 0;
    int incl = v;
    #pragma unroll
    for (int off = 1; off < 32; off <<= 1) {
        int nv = __shfl_up_sync(0xffffffffu, incl, off);
        if (lane >= off) incl += nv;
    }
    __shared__ int wsum[8];
    if (lane == 31) wsum[w] = incl;
    __syncthreads();
    if (t < 8) {
        int xw = wsum[t];
        int in2 = xw;
        #pragma unroll
        for (int off = 1; off < 8; off <<= 1) {
            int nv = __shfl_up_sync(0xffu, in2, off);
            if (t >= off) in2 += nv;
        }
        wsum[t] = in2 - xw;   // exclusive warp offsets
    }
    __syncthreads();
    int excl = incl - v + wsum[w];

    __shared__ int sPrefix;
    __shared__ int sTotal;
    if (t == 255) sTotal = excl + v;
    __syncthreads();
    if (t == 0) {
        unsigned long long total = (unsigned long long)(unsigned)sTotal;
        if (bid == 0) {
            atomicExch(&g_pkt[0], total | FLAG_INCL);
            sPrefix = 0;
        } else {
            atomicExch(&g_pkt[bid], total | FLAG_AGG);
            long long run = 0;
            int j = bid - 1;
            while (true) {
                unsigned long long p;
                do { p = atomicAdd(&g_pkt[j], 0ull); } while ((p >> 32) == 0);
                run += (unsigned)(p & 0xffffffffu);
                if (p & FLAG_INCL) break;
                j--;
            }
            atomicExch(&g_pkt[bid], (total + (unsigned long long)(unsigned)run) | FLAG_INCL);
            sPrefix = (int)run;
        }
    }
    __syncthreads();
    if (g < N) {
        int st = excl + sPrefix;
        g_start[g] = st;
        g_cursor[g] = st;
    }
}

// ---------------------------------------------------------------------------
// Kernel 3: scatter edges into CSR; re-zeroes g_pkt for the next replay.
// ---------------------------------------------------------------------------
__global__ void scatter_kernel(const int* __restrict__ ei, int E) {
    int i = blockIdx.x * blockDim.x + threadIdx.x;
    if (i < SCAN_BLOCKS) g_pkt[i] = 0ull;
    if (i >= E) return;
    int s = ei[i];
    int d = ei[E + i];
    int pos = atomicAdd(&g_cursor[d], 1);
    g_csrc[pos] = s;
}

// ---------------------------------------------------------------------------
// Kernel 4: warp-per-node gather aggregation.
// Each 16-lane half handles alternating edges; the CSR index is broadcast-
// loaded by all 16 lanes (no shuffles in the dependency chain) and the next
// index is prefetched -> >=4 independent L2 chains in flight per warp.
// Block partials red into 64-way-spread slots (no same-line pileup).
// Last-done block sums slots, does the 64x64 matvec, re-zeroes state.
// ---------------------------------------------------------------------------
__global__ void agg_kernel(const float* __restrict__ bias,
                           const float* __restrict__ W_lin, const float* __restrict__ b_lin,
                           float* __restrict__ out, float invN, int N) {
    __shared__ float sm[64];
    __shared__ float sf[64];
    __shared__ int lastFlag;
    int t = threadIdx.x;
    if (t < 64) sm[t] = 0.f;
    __syncthreads();

    int wid = t >> 5, lane = t & 31;
    int half = lane >> 4, l16 = lane & 15;
    int node = blockIdx.x * 8 + wid;

    if (node < N) {
        int deg = g_deg[node];
        int start = g_start[node];
        if (lane == 0) g_deg[node] = 0;        // cleanup for next replay's histogram
        float adst_n = g_adst[node];
        float asrc_n = g_adst == g_asrc ? 0.f : g_asrc[node];
        float4 acc = make_float4(0.f, 0.f, 0.f, 0.f);
        float dsum = 0.f;

        // self loop (half 0 accumulates the feature part)
        float e_self = __expf(lrelu(asrc_n + adst_n));
        if (half == 0) {
            float2 p = __ldg((const float2*)g_h2 + node * 16 + l16);
            float2 lo = __half22float2(((const __half2*)&p)[0]);
            float2 hi = __half22float2(((const __half2*)&p)[1]);
            acc.x = lo.x * e_self; acc.y = lo.y * e_self;
            acc.z = hi.x * e_self; acc.w = hi.y * e_self;
        }

        // edges k = half, half+2, ... ; csrc broadcast-loaded by all 16 lanes
        int k = half;
        int s_next = 0;
        if (k < deg) s_next = __ldg(g_csrc + start + k);
        for (; k < deg; k += 2) {
            int s_cur = s_next;
            int kn = k + 2;
            if (kn < deg) s_next = __ldg(g_csrc + start + kn);
            float e = __expf(lrelu(__ldg(g_asrc + s_cur) + adst_n));
            dsum += e;                                  // same value across the half
            float2 p = __ldg((const float2*)g_h2 + s_cur * 16 + l16);
            float2 lo = __half22float2(((const __half2*)&p)[0]);
            float2 hi = __half22float2(((const __half2*)&p)[1]);
            acc.x += lo.x * e; acc.y += lo.y * e;
            acc.z += hi.x * e; acc.w += hi.y * e;
        }

        // combine the two halves (lane l and l^16 hold the same columns)
        float dother = __shfl_xor_sync(0xffffffffu, dsum, 16);
        float denom = dsum + dother + e_self;
        acc.x += __shfl_xor_sync(0xffffffffu, acc.x, 16);
        acc.y += __shfl_xor_sync(0xffffffffu, acc.y, 16);
        acc.z += __shfl_xor_sync(0xffffffffu, acc.z, 16);
        acc.w += __shfl_xor_sync(0xffffffffu, acc.w, 16);

        if (half == 0) {
            float inv = 1.f / denom;
            float4 bv = ((const float4*)bias)[l16];
            atomicAdd(&sm[l16 * 4 + 0], fmaxf(acc.x * inv + bv.x, 0.f));
            atomicAdd(&sm[l16 * 4 + 1], fmaxf(acc.y * inv + bv.y, 0.f));
            atomicAdd(&sm[l16 * 4 + 2], fmaxf(acc.z * inv + bv.z, 0.f));
            atomicAdd(&sm[l16 * 4 + 3], fmaxf(acc.w * inv + bv.w, 0.f));
        }
    }
    __syncthreads();
    if (t < 16) {
        float4 v = *(float4*)&sm[t * 4];
        float* dst = g_smulti + (blockIdx.x & 63) * 64 + t * 4;   // 64-way spread
        asm volatile("red.global.add.v4.f32 [%0], {%1,%2,%3,%4};"
                     :: "l"(dst), "f"(v.x), "f"(v.y), "f"(v.z), "f"(v.w)
                     : "memory");
        __threadfence();
    }
    __syncthreads();
    if (t == 0) {
        int old = atomicAdd(&g_done, 1);
        lastFlag = (old == (int)gridDim.x - 1);
    }
    __syncthreads();

    if (lastFlag) {
        __threadfence();   // acquire: all blocks' reds visible
        if (t < 64) {
            float v = 0.f;
            #pragma unroll 8
            for (int j = 0; j < 64; j++) {
                float pj;
                asm volatile("ld.global.cg.f32 %0, [%1];" : "=f"(pj) : "l"(g_smulti + j * 64 + t));
                v += pj;
                g_smulti[j * 64 + t] = 0.f;   // cleanup for next replay
            }
            sf[t] = v;
        }
        __syncthreads();
        if (t < 64) {
            float acc2 = b_lin[t];
            #pragma unroll 8
            for (int c = 0; c < 64; c++)
                acc2 += (sf[c] * invN) * W_lin[c * 64 + t];
            out[t] = acc2;
        }
        if (t == 0) g_done = 0;               // cleanup for next replay
    }
}

// ---------------------------------------------------------------------------
extern "C" void kernel_launch(void* const* d_in, const int* in_sizes, int n_in,
                              void* d_out, int out_size) {
    const float* x       = (const float*)d_in[0];
    const int*   ei      = (const int*)d_in[1];
    const float* W       = (const float*)d_in[2];
    const float* att_src = (const float*)d_in[3];
    const float* att_dst = (const float*)d_in[4];
    const float* bias    = (const float*)d_in[5];
    const float* W_lin   = (const float*)d_in[6];
    const float* b_lin   = (const float*)d_in[7];

    int N = in_sizes[0] / 128;   // 100000
    int E = in_sizes[1] / 2;     // 1600000
    int GB = (N + 63) / 64;      // gemm blocks
    int HB = (E + 255) / 256;    // hist blocks

    gemm_hist_kernel<<<GB + HB, 256>>>(x, W, att_src, att_dst, ei, N, E, GB);
    scan_kernel<<<(N + 255) / 256, 256>>>(N);
    scatter_kernel<<<(E + 255) / 256, 256>>>(ei, E);
    agg_kernel<<<(N + 7) / 8, 256>>>(bias, W_lin, b_lin, (float*)d_out, 1.0f / (float)N, N);
}